// round 3
// baseline (speedup 1.0000x reference)
#include <cuda_runtime.h>

#define BB 8
#define NN 2048
#define DD 128
#define LL 3
#define ALPHA 0.2f
#define NEG_INF -9e15f
#define NW 64  /* 32-bit words per adjacency row (N/32) */

// Scratch (device globals: no allocation allowed in kernel_launch)
__device__ float    g_h [BB * NN * DD];      // 8 MB: h = relu(xW+b)
__device__ float    g_s1[BB * NN];
__device__ float    g_s2[BB * NN];
__device__ float    g_m [BB * NN];           // per-row masked max of e
__device__ unsigned g_bits[BB * NN * NW];    // 4 MB: packed adjacency

typedef unsigned long long u64;

// Packed fp32x2 FMA (Blackwell sm_103a): d = a*b + c on both lanes
__device__ __forceinline__ u64 fma2(u64 a, u64 b, u64 c) {
    u64 d;
    asm("fma.rn.f32x2 %0, %1, %2, %3;" : "=l"(d) : "l"(a), "l"(b), "l"(c));
    return d;
}
__device__ __forceinline__ u64 pack2(float lo, float hi) {
    u64 d;
    asm("mov.b64 %0, {%1, %2};" : "=l"(d) : "f"(lo), "f"(hi));
    return d;
}

// ---------------------------------------------------------------------------
// K0: pack adj (int32 {0,1}) into bitmask. One thread per element, ballot.
// ---------------------------------------------------------------------------
__global__ __launch_bounds__(256) void pack_adj_kernel(const int* __restrict__ adj)
{
    int idx = blockIdx.x * 256 + threadIdx.x;       // < B*N*N
    unsigned bit = (adj[idx] > 0) ? 1u : 0u;
    unsigned word = __ballot_sync(0xffffffffu, bit);
    if ((threadIdx.x & 31) == 0) g_bits[idx >> 5] = word;
}

// ---------------------------------------------------------------------------
// K1: h = relu(x @ W + b); s1 = h.a1; s2 = h.a2
// Block: 64 rows x 128 cols, 256 threads, 4x8 register tile per thread.
// ---------------------------------------------------------------------------
__global__ __launch_bounds__(256) void gemm_h_kernel(
    const float* __restrict__ x, const float* __restrict__ Wg,
    const float* __restrict__ bg, const float* __restrict__ aa, int layer)
{
    __shared__ float x_s[64][33];    // pitch 33 -> conflict-free
    __shared__ float W_s[32][128];

    const float* W    = Wg + layer * DD * DD;
    const float* bias = bg + layer * DD;
    const float* a1   = aa + layer * 2 * DD;
    const float* a2   = a1 + DD;

    int t   = threadIdx.x;
    int tr  = t >> 4;        // 0..15
    int tc  = t & 15;        // 0..15
    int row0 = blockIdx.x * 64;

    float acc[4][8];
#pragma unroll
    for (int i = 0; i < 4; i++)
#pragma unroll
        for (int u = 0; u < 8; u++) acc[i][u] = 0.f;

    for (int kc = 0; kc < 4; kc++) {
        __syncthreads();
        {
            int r = t >> 2, q = t & 3;
            const float4* src = (const float4*)(x + (size_t)(row0 + r) * DD + kc * 32 + q * 8);
            float4 v0 = src[0], v1 = src[1];
            float* dst = &x_s[r][q * 8];
            dst[0] = v0.x; dst[1] = v0.y; dst[2] = v0.z; dst[3] = v0.w;
            dst[4] = v1.x; dst[5] = v1.y; dst[6] = v1.z; dst[7] = v1.w;
        }
#pragma unroll
        for (int p = 0; p < 4; p++) {
            int i = t + 256 * p;
            int k = i >> 5, dq = (i & 31) * 4;
            *(float4*)&W_s[k][dq] = *(const float4*)(W + (size_t)(kc * 32 + k) * DD + dq);
        }
        __syncthreads();
#pragma unroll
        for (int k = 0; k < 32; k++) {
            float xv[4], wv[8];
#pragma unroll
            for (int i = 0; i < 4; i++) xv[i] = x_s[tr * 4 + i][k];
#pragma unroll
            for (int u = 0; u < 8; u++) wv[u] = W_s[k][tc + (u << 4)];
#pragma unroll
            for (int i = 0; i < 4; i++)
#pragma unroll
                for (int u = 0; u < 8; u++)
                    acc[i][u] = fmaf(xv[i], wv[u], acc[i][u]);
        }
    }

    float bv[8], a1v[8], a2v[8];
#pragma unroll
    for (int u = 0; u < 8; u++) {
        int d = tc + (u << 4);
        bv[u] = bias[d]; a1v[u] = a1[d]; a2v[u] = a2[d];
    }
#pragma unroll
    for (int i = 0; i < 4; i++) {
        int row = row0 + tr * 4 + i;
        float p1 = 0.f, p2 = 0.f;
#pragma unroll
        for (int u = 0; u < 8; u++) {
            float hv = acc[i][u] + bv[u];
            hv = fmaxf(hv, 0.f);
            g_h[(size_t)row * DD + tc + (u << 4)] = hv;
            p1 = fmaf(hv, a1v[u], p1);
            p2 = fmaf(hv, a2v[u], p2);
        }
#pragma unroll
        for (int off = 8; off; off >>= 1) {
            p1 += __shfl_xor_sync(0xffffffffu, p1, off, 16);
            p2 += __shfl_xor_sync(0xffffffffu, p2, off, 16);
        }
        if (tc == 0) { g_s1[row] = p1; g_s2[row] = p2; }
    }
}

// ---------------------------------------------------------------------------
// K2: per-row masked max.  m_i = lrelu(s1_i + max_{adj[i][j]=1} s2_j),
//     or NEG_INF if the row is fully masked.  One warp per row.
// ---------------------------------------------------------------------------
__global__ __launch_bounds__(256) void rowmax_kernel()
{
    int row  = blockIdx.x * 8 + (threadIdx.x >> 5);
    int lane = threadIdx.x & 31;
    int batch = row >> 11;
    const unsigned* bits = g_bits + (size_t)row * NW;
    const float*    s2   = g_s2 + (batch << 11);

    float mx = -3.0e38f;
#pragma unroll 4
    for (int w = 0; w < NW; w++) {
        unsigned word = bits[w];
        float v = s2[(w << 5) + lane];
        if ((word >> lane) & 1u) mx = fmaxf(mx, v);
    }
#pragma unroll
    for (int off = 16; off; off >>= 1)
        mx = fmaxf(mx, __shfl_xor_sync(0xffffffffu, mx, off));

    if (lane == 0) {
        float m;
        if (mx < -1.0e38f) {
            m = NEG_INF;
        } else {
            float e = g_s1[row] + mx;
            m = (e > 0.f) ? e : ALPHA * e;
        }
        g_m[row] = m;
    }
}

// ---------------------------------------------------------------------------
// K3: fused masked-softmax @ h + residual.  f32x2-packed FMA microkernel.
// Grid (N/32, B) = 512 CTAs (single wave at occ>=4). Block 256 threads
// computes 32 rows x 128 cols; per thread 2 rows x 4 col-pairs.
// Per 32-j chunk: load h tile, compute w = exp(e-m) (duplicated float2 in
// smem), then 8 FFMA2 + 6 LDS.64 per j -> FMA-pipe bound.
// ---------------------------------------------------------------------------
__global__ __launch_bounds__(256, 4) void attn_kernel(float* __restrict__ xio)
{
    __shared__ float  h_s[32][128];
    __shared__ float2 w2_s[32][33];     // [j][row], duplicated (w,w)
    __shared__ float  s1_s[32], m_s[32], zinv_s[32];
    __shared__ float  zbuf[32 * 9];

    int t = threadIdx.x;
    int batch = blockIdx.y;
    int row0  = blockIdx.x * 32;
    int grow0 = (batch << 11) + row0;

    const float* hB  = g_h  + ((size_t)batch << 11) * DD;
    const float* s2B = g_s2 + (batch << 11);

    if (t < 32) { s1_s[t] = g_s1[grow0 + t]; m_s[t] = g_m[grow0 + t]; }

    // phase-1 mapping: one row, four consecutive j per thread
    int p_row = t >> 3;                 // 0..31
    int p_j0  = (t & 7) << 2;           // 0,4,...,28
    const unsigned* bitrow = g_bits + (size_t)(grow0 + p_row) * NW;

    // phase-2 mapping: rows 2tr,2tr+1; cols 2tc+32u
    int tc = t & 15;
    int tr = t >> 4;

    u64 acc[2][4];
#pragma unroll
    for (int i = 0; i < 2; i++)
#pragma unroll
        for (int u = 0; u < 4; u++) acc[i][u] = 0ULL;
    float zpart = 0.f;

    for (int jc = 0; jc < 64; jc++) {
        __syncthreads();                 // prior phase2 done with h_s/w2_s
        // load h tile: 32 x 128 = 1024 float4 / 256 threads
        {
            const float4* src = (const float4*)(hB + (size_t)jc * 32 * DD);
            float4* dst = (float4*)&h_s[0][0];
#pragma unroll
            for (int p = 0; p < 4; p++) dst[t + 256 * p] = src[t + 256 * p];
        }
        // phase 1: w duplicated into smem; z accumulated in registers
        {
            unsigned word = bitrow[jc];
            float4 s2v = *(const float4*)(s2B + (jc << 5) + p_j0);
            float s1v = s1_s[p_row];
            float mv  = m_s[p_row];
            float s2a[4] = {s2v.x, s2v.y, s2v.z, s2v.w};
#pragma unroll
            for (int i = 0; i < 4; i++) {
                float e = s1v + s2a[i];
                e = (e > 0.f) ? e : ALPHA * e;
                if (!((word >> (p_j0 + i)) & 1u)) e = NEG_INF;
                float w = __expf(e - mv);   // masked -> 0; all-masked row -> 1
                zpart += w;
                w2_s[p_j0 + i][p_row] = make_float2(w, w);
            }
        }
        __syncthreads();
        // phase 2: packed rank-1 updates (8 FFMA2 + 6 LDS.64 per j)
#pragma unroll 8
        for (int j = 0; j < 32; j++) {
            u64 w0 = *(const u64*)&w2_s[j][2 * tr];
            u64 w1 = *(const u64*)&w2_s[j][2 * tr + 1];
            u64 hv[4];
#pragma unroll
            for (int u = 0; u < 4; u++)
                hv[u] = *(const u64*)&h_s[j][2 * tc + 32 * u];
#pragma unroll
            for (int u = 0; u < 4; u++) {
                acc[0][u] = fma2(w0, hv[u], acc[0][u]);
                acc[1][u] = fma2(w1, hv[u], acc[1][u]);
            }
        }
    }

    // Z reduction: 8 partials per row -> invZ
    __syncthreads();
    zbuf[p_row * 9 + (t & 7)] = zpart;
    __syncthreads();
    if (t < 32) {
        float z = 0.f;
#pragma unroll
        for (int k = 0; k < 8; k++) z += zbuf[t * 9 + k];
        zinv_s[t] = 1.0f / z;
    }
    __syncthreads();

    // epilogue: x += acc * invZ   (packed)
#pragma unroll
    for (int i = 0; i < 2; i++) {
        int r = 2 * tr + i;
        float iz = zinv_s[r];
        u64 iz2 = pack2(iz, iz);
        size_t base = (size_t)(grow0 + r) * DD;
#pragma unroll
        for (int u = 0; u < 4; u++) {
            u64* p = (u64*)&xio[base + 2 * tc + 32 * u];
            *p = fma2(acc[i][u], iz2, *p);
        }
    }
}

// ---------------------------------------------------------------------------
extern "C" void kernel_launch(void* const* d_in, const int* in_sizes, int n_in,
                              void* d_out, int out_size)
{
    const float* x   = (const float*)d_in[0];   // [B,N,D]
    const int*   adj = (const int*)  d_in[1];   // [B,N,N]
    const float* Wg  = (const float*)d_in[2];   // [L,D,D]
    const float* bg  = (const float*)d_in[3];   // [L,D]
    const float* aa  = (const float*)d_in[4];   // [L,2D]
    float* out = (float*)d_out;                 // [B,N,D] -- evolving x

    cudaMemcpyAsync(out, x, (size_t)BB * NN * DD * sizeof(float),
                    cudaMemcpyDeviceToDevice);

    pack_adj_kernel<<<(BB * NN * NN) / 256, 256>>>(adj);

    for (int l = 0; l < LL; l++) {
        gemm_h_kernel<<<(BB * NN) / 64, 256>>>(out, Wg, bg, aa, l);
        rowmax_kernel<<<(BB * NN) / 8, 256>>>();
        attn_kernel<<<dim3(NN / 32, BB), 256>>>(out);
    }
}

// round 9
// speedup vs baseline: 3.5620x; 3.5620x over previous
#include <cuda_runtime.h>
#include <cuda_bf16.h>
#include <cstdint>

#define BB 8
#define NN 2048
#define DD 128
#define LL 3
#define ALPHA 0.2f
#define NEG_INF -9e15f
#define NW 64  /* 32-bit words per adjacency row (N/32) */

// Scratch (device globals: no allocation allowed in kernel_launch)
__device__ __align__(16) float          g_h [BB * NN * DD];   // 8 MB fp32 h
__device__ __align__(16) __nv_bfloat16  g_hT[BB * DD * NN];   // 4 MB bf16 h^T
__device__ float    g_s1[BB * NN];
__device__ float    g_s2[BB * NN];
__device__ float    g_m [BB * NN];
__device__ unsigned g_bits[BB * NN * NW];                     // 4 MB packed adj

// ======================= helpers ============================
__device__ __forceinline__ uint32_t smem_u32(const void* p) {
    uint32_t a;
    asm("{ .reg .u64 t; cvta.to.shared.u64 t, %1; cvt.u32.u64 %0, t; }"
        : "=r"(a) : "l"(p));
    return a;
}
__device__ __forceinline__ void sts128(uint32_t a, uint32_t x, uint32_t y,
                                       uint32_t z, uint32_t w) {
    asm volatile("st.shared.v4.b32 [%0], {%1,%2,%3,%4};"
                 :: "r"(a), "r"(x), "r"(y), "r"(z), "r"(w) : "memory");
}
__device__ __forceinline__ uint32_t bf16pack(float lo, float hi) {
    uint32_t r;
    asm("cvt.rn.bf16x2.f32 %0, %1, %2;" : "=r"(r) : "f"(hi), "f"(lo));
    return r;
}
__device__ __forceinline__ void ldsm4(uint32_t* r, uint32_t a) {
    asm volatile("ldmatrix.sync.aligned.m8n8.x4.shared.b16 {%0,%1,%2,%3}, [%4];"
                 : "=r"(r[0]), "=r"(r[1]), "=r"(r[2]), "=r"(r[3]) : "r"(a));
}
__device__ __forceinline__ void mma16816(float* c, const uint32_t* a,
                                         uint32_t b0, uint32_t b1) {
    asm volatile("mma.sync.aligned.m16n8k16.row.col.f32.bf16.bf16.f32 "
                 "{%0,%1,%2,%3}, {%4,%5,%6,%7}, {%8,%9}, {%0,%1,%2,%3};"
                 : "+f"(c[0]), "+f"(c[1]), "+f"(c[2]), "+f"(c[3])
                 : "r"(a[0]), "r"(a[1]), "r"(a[2]), "r"(a[3]),
                   "r"(b0), "r"(b1));
}

// ---------------------------------------------------------------------------
// K0: pack adj into bitmask
// ---------------------------------------------------------------------------
__global__ __launch_bounds__(256) void pack_adj_kernel(const int* __restrict__ adj)
{
    int idx = blockIdx.x * 256 + threadIdx.x;
    unsigned bit = (adj[idx] > 0) ? 1u : 0u;
    unsigned word = __ballot_sync(0xffffffffu, bit);
    if ((threadIdx.x & 31) == 0) g_bits[idx >> 5] = word;
}

// ---------------------------------------------------------------------------
// K1: h = relu(x @ W + b); s1 = h.a1; s2 = h.a2
// ---------------------------------------------------------------------------
__global__ __launch_bounds__(256) void gemm_h_kernel(
    const float* __restrict__ x, const float* __restrict__ Wg,
    const float* __restrict__ bg, const float* __restrict__ aa, int layer)
{
    __shared__ float x_s[64][33];
    __shared__ float W_s[32][128];

    const float* W    = Wg + layer * DD * DD;
    const float* bias = bg + layer * DD;
    const float* a1   = aa + layer * 2 * DD;
    const float* a2   = a1 + DD;

    int t   = threadIdx.x;
    int tr  = t >> 4;
    int tc  = t & 15;
    int row0 = blockIdx.x * 64;

    float acc[4][8];
#pragma unroll
    for (int i = 0; i < 4; i++)
#pragma unroll
        for (int u = 0; u < 8; u++) acc[i][u] = 0.f;

    for (int kc = 0; kc < 4; kc++) {
        __syncthreads();
        {
            int r = t >> 2, q = t & 3;
            const float4* src = (const float4*)(x + (size_t)(row0 + r) * DD + kc * 32 + q * 8);
            float4 v0 = src[0], v1 = src[1];
            float* dst = &x_s[r][q * 8];
            dst[0] = v0.x; dst[1] = v0.y; dst[2] = v0.z; dst[3] = v0.w;
            dst[4] = v1.x; dst[5] = v1.y; dst[6] = v1.z; dst[7] = v1.w;
        }
#pragma unroll
        for (int p = 0; p < 4; p++) {
            int i = t + 256 * p;
            int k = i >> 5, dq = (i & 31) * 4;
            *(float4*)&W_s[k][dq] = *(const float4*)(W + (size_t)(kc * 32 + k) * DD + dq);
        }
        __syncthreads();
#pragma unroll
        for (int k = 0; k < 32; k++) {
            float xv[4], wv[8];
#pragma unroll
            for (int i = 0; i < 4; i++) xv[i] = x_s[tr * 4 + i][k];
#pragma unroll
            for (int u = 0; u < 8; u++) wv[u] = W_s[k][tc + (u << 4)];
#pragma unroll
            for (int i = 0; i < 4; i++)
#pragma unroll
                for (int u = 0; u < 8; u++)
                    acc[i][u] = fmaf(xv[i], wv[u], acc[i][u]);
        }
    }

    float bv[8], a1v[8], a2v[8];
#pragma unroll
    for (int u = 0; u < 8; u++) {
        int d = tc + (u << 4);
        bv[u] = bias[d]; a1v[u] = a1[d]; a2v[u] = a2[d];
    }
#pragma unroll
    for (int i = 0; i < 4; i++) {
        int row = row0 + tr * 4 + i;
        float p1 = 0.f, p2 = 0.f;
#pragma unroll
        for (int u = 0; u < 8; u++) {
            float hv = acc[i][u] + bv[u];
            hv = fmaxf(hv, 0.f);
            g_h[(size_t)row * DD + tc + (u << 4)] = hv;
            p1 = fmaf(hv, a1v[u], p1);
            p2 = fmaf(hv, a2v[u], p2);
        }
#pragma unroll
        for (int off = 8; off; off >>= 1) {
            p1 += __shfl_xor_sync(0xffffffffu, p1, off, 16);
            p2 += __shfl_xor_sync(0xffffffffu, p2, off, 16);
        }
        if (tc == 0) { g_s1[row] = p1; g_s2[row] = p2; }
    }
}

// ---------------------------------------------------------------------------
// K1b: transpose h (fp32 [B][N][D]) -> hT (bf16 [B][D][N])
// ---------------------------------------------------------------------------
__global__ __launch_bounds__(256) void transpose_h_kernel()
{
    __shared__ float tile[32][33];
    int jt = blockIdx.x * 32, dt = blockIdx.y * 32, b = blockIdx.z;
    int lx = threadIdx.x & 31, ly = threadIdx.x >> 5;   // 32 x 8

    const float* src = g_h + ((size_t)b * NN + jt) * DD + dt;
#pragma unroll
    for (int p = 0; p < 4; p++)
        tile[ly + 8 * p][lx] = src[(size_t)(ly + 8 * p) * DD + lx];
    __syncthreads();
    __nv_bfloat16* dst = g_hT + ((size_t)b * DD + dt) * NN + jt;
#pragma unroll
    for (int p = 0; p < 4; p++) {
        int d = ly + 8 * p;
        dst[(size_t)d * NN + lx] = __float2bfloat16(tile[lx][d]);
    }
}

// ---------------------------------------------------------------------------
// K2: per-row masked max
// ---------------------------------------------------------------------------
__global__ __launch_bounds__(256) void rowmax_kernel()
{
    int row  = blockIdx.x * 8 + (threadIdx.x >> 5);
    int lane = threadIdx.x & 31;
    int batch = row >> 11;
    const unsigned* bits = g_bits + (size_t)row * NW;
    const float*    s2   = g_s2 + (batch << 11);

    float mx = -3.0e38f;
#pragma unroll 4
    for (int w = 0; w < NW; w++) {
        unsigned word = bits[w];
        float v = s2[(w << 5) + lane];
        if ((word >> lane) & 1u) mx = fmaxf(mx, v);
    }
#pragma unroll
    for (int off = 16; off; off >>= 1)
        mx = fmaxf(mx, __shfl_xor_sync(0xffffffffu, mx, off));

    if (lane == 0) {
        float m;
        if (mx < -1.0e38f) m = NEG_INF;
        else {
            float e = g_s1[row] + mx;
            m = (e > 0.f) ? e : ALPHA * e;
        }
        g_m[row] = m;
    }
}

// ---------------------------------------------------------------------------
// K3: HMMA (mma.sync bf16) fused masked-softmax @ h + residual.
// CTA: 128 query rows x 128 d. 8 warps, warp = 16 rows x 128 d.
// K-loop: 64 chunks of 32 j. P tile generated (masked exp, bf16), H tile
// copied from g_hT (bf16, k-contiguous = col-major B). fp32 accumulators.
// Smem pitch 80B -> conflict-free ldmatrix (r*5 mod 8 is a permutation).
// ---------------------------------------------------------------------------
#define PITCHB 80   /* bytes per smem tile row (32 bf16 + 16B pad) */

__global__ __launch_bounds__(256, 1) void attn_kernel(float* __restrict__ xio)
{
    __shared__ __align__(16) char A_s[128 * PITCHB];   // P tile
    __shared__ __align__(16) char B_s[128 * PITCHB];   // H^T tile
    __shared__ float zbuf[256];
    __shared__ float zi[128];

    int t = threadIdx.x, lane = t & 31, w = t >> 5;
    int batch = blockIdx.y;
    int row0  = blockIdx.x * 128;
    int grow0 = (batch << 11) + row0;

    // generation mapping: row/d = t>>1, half (16 j) = t&1
    int prow = t >> 1, jh = t & 1;
    float s1v = g_s1[grow0 + prow];
    float mv  = g_m [grow0 + prow];
    const unsigned* bitrow = g_bits + (size_t)(grow0 + prow) * NW;
    const float* s2B = g_s2 + (batch << 11);
    const __nv_bfloat16* hsrc =
        g_hT + (size_t)batch * DD * NN + (size_t)prow * NN + jh * 16;

    uint32_t aA = smem_u32(A_s), aB = smem_u32(B_s);
    uint32_t stA = aA + prow * PITCHB + jh * 32;
    uint32_t stB = aB + prow * PITCHB + jh * 32;

    // ldmatrix source addresses (per warp)
    uint32_t lmA = aA + (uint32_t)(w * 16 + (lane & 15)) * PITCHB
                      + ((lane >> 4) & 1) * 16;
    uint32_t lmB = aB + (uint32_t)(lane & 15) * PITCHB
                      + ((lane >> 4) & 1) * 16;

    float acc[16][4];
#pragma unroll
    for (int n = 0; n < 16; n++)
#pragma unroll
        for (int q = 0; q < 4; q++) acc[n][q] = 0.f;
    float zpart = 0.f;

    // prefetch chunk 0
    uint4  hp0 = *(const uint4*)(hsrc);
    uint4  hp1 = *(const uint4*)(hsrc + 8);
    float4 sp[4];
#pragma unroll
    for (int u = 0; u < 4; u++)
        sp[u] = *(const float4*)(s2B + jh * 16 + u * 4);
    unsigned wp = bitrow[0];

    for (int i = 0; i < 64; i++) {
        __syncthreads();                 // previous mma phase done with smem
        // ---- store H tile ----
        sts128(stB,      hp0.x, hp0.y, hp0.z, hp0.w);
        sts128(stB + 16, hp1.x, hp1.y, hp1.z, hp1.w);
        // ---- compute + store P tile ----
        {
            uint32_t pk[8];
#pragma unroll
            for (int u = 0; u < 4; u++) {
                float sv[4] = { sp[u].x, sp[u].y, sp[u].z, sp[u].w };
                float ww[4];
#pragma unroll
                for (int k = 0; k < 4; k++) {
                    float e = s1v + sv[k];
                    e = (e > 0.f) ? e : ALPHA * e;
                    if (!((wp >> (jh * 16 + u * 4 + k)) & 1u)) e = NEG_INF;
                    float v = __expf(e - mv);   // masked->0; all-masked row->1
                    zpart += v;
                    ww[k] = v;
                }
                pk[u * 2 + 0] = bf16pack(ww[0], ww[1]);
                pk[u * 2 + 1] = bf16pack(ww[2], ww[3]);
            }
            sts128(stA,      pk[0], pk[1], pk[2], pk[3]);
            sts128(stA + 16, pk[4], pk[5], pk[6], pk[7]);
        }
        // ---- prefetch chunk i+1 (redundant reload of 63 at the end) ----
        {
            int inext = (i < 63) ? i + 1 : 63;
            const __nv_bfloat16* hn = hsrc + inext * 32;
            hp0 = *(const uint4*)(hn);
            hp1 = *(const uint4*)(hn + 8);
#pragma unroll
            for (int u = 0; u < 4; u++)
                sp[u] = *(const float4*)(s2B + inext * 32 + jh * 16 + u * 4);
            wp = bitrow[inext];
        }
        __syncthreads();
        // ---- mma phase: 2 k-steps x (A ldsm + 8 B ldsm + 16 HMMA) ----
#pragma unroll
        for (int ks = 0; ks < 2; ks++) {
            uint32_t a[4];
            ldsm4(a, lmA + ks * 32);
#pragma unroll
            for (int ntp = 0; ntp < 8; ntp++) {
                uint32_t b[4];
                ldsm4(b, lmB + ntp * 16 * PITCHB + ks * 32);
                mma16816(acc[2 * ntp],     a, b[0], b[2]);
                mma16816(acc[2 * ntp + 1], a, b[1], b[3]);
            }
        }
    }

    // ---- Z reduction ----
    zbuf[jh * 128 + prow] = zpart;
    __syncthreads();
    if (t < 128) zi[t] = 1.0f / (zbuf[t] + zbuf[128 + t]);
    __syncthreads();

    // ---- epilogue: out = x + acc * invZ ----
    {
        int qr = lane >> 2, qc = lane & 3;
        int r0 = w * 16 + qr;
        float iz0 = zi[r0], iz1 = zi[r0 + 8];
        float* out0 = xio + (size_t)(grow0 + r0) * DD;
        float* out1 = out0 + 8 * DD;
#pragma unroll
        for (int nt = 0; nt < 16; nt++) {
            int col = nt * 8 + qc * 2;
            float2* p0 = (float2*)(out0 + col);
            float2 v0 = *p0;
            v0.x = fmaf(acc[nt][0], iz0, v0.x);
            v0.y = fmaf(acc[nt][1], iz0, v0.y);
            *p0 = v0;
            float2* p1 = (float2*)(out1 + col);
            float2 v1 = *p1;
            v1.x = fmaf(acc[nt][2], iz1, v1.x);
            v1.y = fmaf(acc[nt][3], iz1, v1.y);
            *p1 = v1;
        }
    }
}

// ---------------------------------------------------------------------------
extern "C" void kernel_launch(void* const* d_in, const int* in_sizes, int n_in,
                              void* d_out, int out_size)
{
    const float* x   = (const float*)d_in[0];
    const int*   adj = (const int*)  d_in[1];
    const float* Wg  = (const float*)d_in[2];
    const float* bg  = (const float*)d_in[3];
    const float* aa  = (const float*)d_in[4];
    float* out = (float*)d_out;

    cudaMemcpyAsync(out, x, (size_t)BB * NN * DD * sizeof(float),
                    cudaMemcpyDeviceToDevice);

    pack_adj_kernel<<<(BB * NN * NN) / 256, 256>>>(adj);

    for (int l = 0; l < LL; l++) {
        gemm_h_kernel<<<(BB * NN) / 64, 256>>>(out, Wg, bg, aa, l);
        transpose_h_kernel<<<dim3(NN / 32, DD / 32, BB), 256>>>();
        rowmax_kernel<<<(BB * NN) / 8, 256>>>();
        attn_kernel<<<dim3(NN / 128, BB), 256>>>(out);
    }
}

// round 12
// speedup vs baseline: 5.2557x; 1.4755x over previous
#include <cuda_runtime.h>
#include <cuda_bf16.h>
#include <cstdint>

#define BB 8
#define NN 2048
#define DD 128
#define LL 3
#define ALPHA 0.2f
#define NEG_INF -9e15f
#define NW 64  /* 32-bit words per adjacency row (N/32) */

// Scratch (device globals: no allocation allowed in kernel_launch)
__device__ __align__(16) __nv_bfloat16  g_hT[BB * DD * NN];   // 4 MB bf16 h^T
__device__ float    g_s1[BB * NN];
__device__ float    g_s2[BB * NN];
__device__ float    g_mb[BB];                                 // per-batch max s2
__device__ unsigned g_bits[BB * NN * NW];                     // 4 MB packed adj

// ======================= helpers ============================
__device__ __forceinline__ uint32_t smem_u32(const void* p) {
    uint32_t a;
    asm("{ .reg .u64 t; cvta.to.shared.u64 t, %1; cvt.u32.u64 %0, t; }"
        : "=r"(a) : "l"(p));
    return a;
}
__device__ __forceinline__ void sts128(uint32_t a, uint32_t x, uint32_t y,
                                       uint32_t z, uint32_t w) {
    asm volatile("st.shared.v4.b32 [%0], {%1,%2,%3,%4};"
                 :: "r"(a), "r"(x), "r"(y), "r"(z), "r"(w) : "memory");
}
__device__ __forceinline__ uint32_t bf16pack(float lo, float hi) {
    uint32_t r;
    asm("cvt.rn.bf16x2.f32 %0, %1, %2;" : "=r"(r) : "f"(hi), "f"(lo));
    return r;
}
__device__ __forceinline__ void ldsm4(uint32_t* r, uint32_t a) {
    asm volatile("ldmatrix.sync.aligned.m8n8.x4.shared.b16 {%0,%1,%2,%3}, [%4];"
                 : "=r"(r[0]), "=r"(r[1]), "=r"(r[2]), "=r"(r[3]) : "r"(a));
}
__device__ __forceinline__ void mma16816(float* c, const uint32_t* a,
                                         uint32_t b0, uint32_t b1) {
    asm volatile("mma.sync.aligned.m16n8k16.row.col.f32.bf16.bf16.f32 "
                 "{%0,%1,%2,%3}, {%4,%5,%6,%7}, {%8,%9}, {%0,%1,%2,%3};"
                 : "+f"(c[0]), "+f"(c[1]), "+f"(c[2]), "+f"(c[3])
                 : "r"(a[0]), "r"(a[1]), "r"(a[2]), "r"(a[3]),
                   "r"(b0), "r"(b1));
}

// ---------------------------------------------------------------------------
// K0: pack adj into bitmask. 8 elems/thread (2x int4), byte-shuffle assembly.
// ---------------------------------------------------------------------------
__global__ __launch_bounds__(256) void pack_adj_kernel(const int4* __restrict__ adj4)
{
    int tid = blockIdx.x * 256 + threadIdx.x;     // handles elems 8*tid..+7
    int4 v0 = adj4[2 * tid];
    int4 v1 = adj4[2 * tid + 1];
    unsigned byte =
        (unsigned)(v0.x > 0)        | ((unsigned)(v0.y > 0) << 1) |
        ((unsigned)(v0.z > 0) << 2) | ((unsigned)(v0.w > 0) << 3) |
        ((unsigned)(v1.x > 0) << 4) | ((unsigned)(v1.y > 0) << 5) |
        ((unsigned)(v1.z > 0) << 6) | ((unsigned)(v1.w > 0) << 7);
    unsigned val = byte << (8 * (threadIdx.x & 3));
    val |= __shfl_xor_sync(0xffffffffu, val, 1);
    val |= __shfl_xor_sync(0xffffffffu, val, 2);
    if ((threadIdx.x & 3) == 0) g_bits[tid >> 2] = val;
}

// ---------------------------------------------------------------------------
// K1: h = relu(x @ W + b); s1 = h.a1; s2 = h.a2; and write bf16 h^T directly
// (transpose fused via smem staging tile) -> no fp32 h, no transpose kernel.
// ---------------------------------------------------------------------------
#define HSP 72   /* hstage pitch in bf16: 144 bytes, 16B-aligned rows */

__global__ __launch_bounds__(256) void gemm_h_kernel(
    const float* __restrict__ x, const float* __restrict__ Wg,
    const float* __restrict__ bg, const float* __restrict__ aa, int layer)
{
    __shared__ float x_s[64][33];
    __shared__ float W_s[32][128];
    __shared__ __align__(16) __nv_bfloat16 hstage[128][HSP]; // [d][row_local]

    const float* W    = Wg + layer * DD * DD;
    const float* bias = bg + layer * DD;
    const float* a1   = aa + layer * 2 * DD;
    const float* a2   = a1 + DD;

    int t   = threadIdx.x;
    int tr  = t >> 4;
    int tc  = t & 15;
    int row0 = blockIdx.x * 64;
    int batch = row0 >> 11;
    int jloc  = row0 & (NN - 1);

    float acc[4][8];
#pragma unroll
    for (int i = 0; i < 4; i++)
#pragma unroll
        for (int u = 0; u < 8; u++) acc[i][u] = 0.f;

    for (int kc = 0; kc < 4; kc++) {
        __syncthreads();
        {
            int r = t >> 2, q = t & 3;
            const float4* src = (const float4*)(x + (size_t)(row0 + r) * DD + kc * 32 + q * 8);
            float4 v0 = src[0], v1 = src[1];
            float* dst = &x_s[r][q * 8];
            dst[0] = v0.x; dst[1] = v0.y; dst[2] = v0.z; dst[3] = v0.w;
            dst[4] = v1.x; dst[5] = v1.y; dst[6] = v1.z; dst[7] = v1.w;
        }
#pragma unroll
        for (int p = 0; p < 4; p++) {
            int i = t + 256 * p;
            int k = i >> 5, dq = (i & 31) * 4;
            *(float4*)&W_s[k][dq] = *(const float4*)(W + (size_t)(kc * 32 + k) * DD + dq);
        }
        __syncthreads();
#pragma unroll
        for (int k = 0; k < 32; k++) {
            float xv[4], wv[8];
#pragma unroll
            for (int i = 0; i < 4; i++) xv[i] = x_s[tr * 4 + i][k];
#pragma unroll
            for (int u = 0; u < 8; u++) wv[u] = W_s[k][tc + (u << 4)];
#pragma unroll
            for (int i = 0; i < 4; i++)
#pragma unroll
                for (int u = 0; u < 8; u++)
                    acc[i][u] = fmaf(xv[i], wv[u], acc[i][u]);
        }
    }

    float bv[8], a1v[8], a2v[8];
#pragma unroll
    for (int u = 0; u < 8; u++) {
        int d = tc + (u << 4);
        bv[u] = bias[d]; a1v[u] = a1[d]; a2v[u] = a2[d];
    }
    float hv[4][8];
#pragma unroll
    for (int i = 0; i < 4; i++)
#pragma unroll
        for (int u = 0; u < 8; u++)
            hv[i][u] = fmaxf(acc[i][u] + bv[u], 0.f);

    // s1/s2 row reductions
#pragma unroll
    for (int i = 0; i < 4; i++) {
        int row = row0 + tr * 4 + i;
        float p1 = 0.f, p2 = 0.f;
#pragma unroll
        for (int u = 0; u < 8; u++) {
            p1 = fmaf(hv[i][u], a1v[u], p1);
            p2 = fmaf(hv[i][u], a2v[u], p2);
        }
#pragma unroll
        for (int off = 8; off; off >>= 1) {
            p1 += __shfl_xor_sync(0xffffffffu, p1, off, 16);
            p2 += __shfl_xor_sync(0xffffffffu, p2, off, 16);
        }
        if (tc == 0) { g_s1[row] = p1; g_s2[row] = p2; }
    }

    // stage bf16 transposed: hstage[d][row_local]
#pragma unroll
    for (int u = 0; u < 8; u++) {
        uint32_t lo = bf16pack(hv[0][u], hv[1][u]);
        uint32_t hi = bf16pack(hv[2][u], hv[3][u]);
        uint2 pkt; pkt.x = lo; pkt.y = hi;
        *(uint2*)&hstage[tc + (u << 4)][tr * 4] = pkt;
    }
    __syncthreads();

    // write out: thread t -> d = t>>1, 32 contiguous j
    {
        int d = t >> 1, half = t & 1;
        const uint4* src = (const uint4*)&hstage[d][half * 32];
        uint4 v0 = src[0], v1 = src[1], v2 = src[2], v3 = src[3];
        uint4* dst = (uint4*)(g_hT + (size_t)batch * DD * NN + (size_t)d * NN
                              + jloc + half * 32);
        dst[0] = v0; dst[1] = v1; dst[2] = v2; dst[3] = v3;
    }
}

// ---------------------------------------------------------------------------
// K2: per-batch max of s2 (any upper bound works for softmax stability;
// ratios are invariant to the shift, so this is exact math-wise).
// ---------------------------------------------------------------------------
__global__ __launch_bounds__(256) void batchmax_kernel()
{
    __shared__ float red[8];
    int b = blockIdx.x, t = threadIdx.x;
    const float* s2 = g_s2 + (b << 11);
    float mx = -3.0e38f;
#pragma unroll
    for (int k = 0; k < 8; k++) mx = fmaxf(mx, s2[t + 256 * k]);
#pragma unroll
    for (int off = 16; off; off >>= 1)
        mx = fmaxf(mx, __shfl_xor_sync(0xffffffffu, mx, off));
    if ((t & 31) == 0) red[t >> 5] = mx;
    __syncthreads();
    if (t == 0) {
        float m = red[0];
#pragma unroll
        for (int k = 1; k < 8; k++) m = fmaxf(m, red[k]);
        g_mb[b] = m;
    }
}

// ---------------------------------------------------------------------------
// K3: HMMA fused masked-softmax @ h + residual.
// CTA: 128 rows x 128 d, 8 warps in 4x2 grid, warp tile 32 rows x 64 cols
// (B tile read 4x instead of 8x). Double-buffered A/B smem, ONE barrier
// per 32-j chunk. P generated in place (masked exp, bf16); H copied bf16.
// ---------------------------------------------------------------------------
#define PITCHB 80                /* 32 bf16 + 16B pad: ldsm conflict-free */
#define TILEB  (128 * PITCHB)    /* 10240 bytes per tile */

__global__ __launch_bounds__(256, 1) void attn_kernel(float* __restrict__ xio)
{
    __shared__ __align__(16) char AB_s[4 * TILEB];   // A0 A1 B0 B1
    __shared__ float zbuf[256];
    __shared__ float zi[128];

    int t = threadIdx.x, lane = t & 31, w = t >> 5;
    int wr = w >> 1, wc = w & 1;
    int batch = blockIdx.y;
    int row0  = blockIdx.x * 128;
    int grow0 = (batch << 11) + row0;

    // generation mapping: row/d = t>>1, half (16 j) = t&1
    int prow = t >> 1, jh = t & 1;
    float s1v = g_s1[grow0 + prow];
    float mbv = g_mb[batch];
    float me  = s1v + mbv;
    float mv  = (me > 0.f) ? me : ALPHA * me;   // lrelu(s1 + max s2) >= all e
    const unsigned* bitrow = g_bits + (size_t)(grow0 + prow) * NW;
    const float* s2B = g_s2 + (batch << 11);
    const __nv_bfloat16* hsrc =
        g_hT + (size_t)batch * DD * NN + (size_t)prow * NN + jh * 16;

    uint32_t base = smem_u32(AB_s);
    uint32_t stA = base + prow * PITCHB + jh * 32;
    uint32_t stB = base + 2 * TILEB + prow * PITCHB + jh * 32;
    uint32_t lmA = base + (uint32_t)(wr * 32 + (lane & 15)) * PITCHB
                        + ((lane >> 4) & 1) * 16;
    uint32_t lmB = base + 2 * TILEB + (uint32_t)(wc * 64 + (lane & 15)) * PITCHB
                        + ((lane >> 4) & 1) * 16;

    float acc[2][8][4];
#pragma unroll
    for (int mt = 0; mt < 2; mt++)
#pragma unroll
        for (int n = 0; n < 8; n++)
#pragma unroll
            for (int q = 0; q < 4; q++) acc[mt][n][q] = 0.f;
    float zpart = 0.f;

    // prefetch chunk 0
    uint4  hp0 = *(const uint4*)(hsrc);
    uint4  hp1 = *(const uint4*)(hsrc + 8);
    float4 sp[4];
#pragma unroll
    for (int u = 0; u < 4; u++)
        sp[u] = *(const float4*)(s2B + jh * 16 + u * 4);
    unsigned wp = bitrow[0];

    for (int i = 0; i < 64; i++) {
        uint32_t off = (uint32_t)(i & 1) * TILEB;
        // ---- store H tile ----
        sts128(stB + off,      hp0.x, hp0.y, hp0.z, hp0.w);
        sts128(stB + off + 16, hp1.x, hp1.y, hp1.z, hp1.w);
        // ---- compute + store P tile ----
        {
            uint32_t pk[8];
#pragma unroll
            for (int u = 0; u < 4; u++) {
                float sv[4] = { sp[u].x, sp[u].y, sp[u].z, sp[u].w };
                float ww[4];
#pragma unroll
                for (int k = 0; k < 4; k++) {
                    float e = s1v + sv[k];
                    e = (e > 0.f) ? e : ALPHA * e;
                    if (!((wp >> (jh * 16 + u * 4 + k)) & 1u)) e = NEG_INF;
                    float v = __expf(e - mv);   // masked -> 0
                    zpart += v;
                    ww[k] = v;
                }
                pk[u * 2 + 0] = bf16pack(ww[0], ww[1]);
                pk[u * 2 + 1] = bf16pack(ww[2], ww[3]);
            }
            sts128(stA + off,      pk[0], pk[1], pk[2], pk[3]);
            sts128(stA + off + 16, pk[4], pk[5], pk[6], pk[7]);
        }
        // ---- prefetch chunk i+1 ----
        {
            int inext = (i < 63) ? i + 1 : 63;
            const __nv_bfloat16* hn = hsrc + inext * 32;
            hp0 = *(const uint4*)(hn);
            hp1 = *(const uint4*)(hn + 8);
#pragma unroll
            for (int u = 0; u < 4; u++)
                sp[u] = *(const float4*)(s2B + inext * 32 + jh * 16 + u * 4);
            wp = bitrow[inext];
        }
        __syncthreads();   // buf(i) ready; prior reads of this buf already done
        // ---- mma: warp tile 32 rows x 64 cols ----
#pragma unroll
        for (int ks = 0; ks < 2; ks++) {
            uint32_t a0[4], a1[4];
            ldsm4(a0, lmA + off + ks * 32);
            ldsm4(a1, lmA + off + 16 * PITCHB + ks * 32);
#pragma unroll
            for (int g = 0; g < 4; g++) {
                uint32_t b[4];
                ldsm4(b, lmB + off + g * 16 * PITCHB + ks * 32);
                mma16816(acc[0][2 * g],     a0, b[0], b[2]);
                mma16816(acc[0][2 * g + 1], a0, b[1], b[3]);
                mma16816(acc[1][2 * g],     a1, b[0], b[2]);
                mma16816(acc[1][2 * g + 1], a1, b[1], b[3]);
            }
        }
    }

    // ---- Z reduction ----
    zbuf[jh * 128 + prow] = zpart;
    __syncthreads();
    if (t < 128) zi[t] = 1.0f / (zbuf[t] + zbuf[128 + t]);
    __syncthreads();

    // ---- epilogue: out = x + acc * invZ ----
    {
        int qr = lane >> 2, qc = lane & 3;
#pragma unroll
        for (int mt = 0; mt < 2; mt++) {
            int r0 = wr * 32 + mt * 16 + qr;
            float iza = zi[r0], izb = zi[r0 + 8];
            float* o0 = xio + (size_t)(grow0 + r0) * DD + wc * 64;
            float* o1 = o0 + 8 * DD;
#pragma unroll
            for (int nt = 0; nt < 8; nt++) {
                int col = nt * 8 + qc * 2;
                float2* p0 = (float2*)(o0 + col);
                float2 v0 = *p0;
                v0.x = fmaf(acc[mt][nt][0], iza, v0.x);
                v0.y = fmaf(acc[mt][nt][1], iza, v0.y);
                *p0 = v0;
                float2* p1 = (float2*)(o1 + col);
                float2 v1 = *p1;
                v1.x = fmaf(acc[mt][nt][2], izb, v1.x);
                v1.y = fmaf(acc[mt][nt][3], izb, v1.y);
                *p1 = v1;
            }
        }
    }
}

// ---------------------------------------------------------------------------
extern "C" void kernel_launch(void* const* d_in, const int* in_sizes, int n_in,
                              void* d_out, int out_size)
{
    const float* x   = (const float*)d_in[0];
    const int*   adj = (const int*)  d_in[1];
    const float* Wg  = (const float*)d_in[2];
    const float* bg  = (const float*)d_in[3];
    const float* aa  = (const float*)d_in[4];
    float* out = (float*)d_out;

    cudaMemcpyAsync(out, x, (size_t)BB * NN * DD * sizeof(float),
                    cudaMemcpyDeviceToDevice);

    pack_adj_kernel<<<(BB * NN * NN) / (8 * 256), 256>>>((const int4*)adj);

    for (int l = 0; l < LL; l++) {
        gemm_h_kernel<<<(BB * NN) / 64, 256>>>(out, Wg, bg, aa, l);
        batchmax_kernel<<<BB, 256>>>();
        attn_kernel<<<dim3(NN / 128, BB), 256>>>(out);
    }
}